// round 6
// baseline (speedup 1.0000x reference)
#include <cuda_runtime.h>
#include <math.h>
#include <stdint.h>

#define N_NODES 50000
#define N_EDGES 800000
#define IN_F    256
#define HID     64
#define CAT_F   256   // 4 * HID

// ---------------- static scratch (no allocations allowed) ----------------
__device__ int   g_cnt_in [N_NODES];
__device__ int   g_cnt_out[N_NODES];
__device__ int   g_cursor [N_NODES];
__device__ int   g_csr_off[N_NODES + 1];
__device__ int   g_esrc   [N_EDGES];
__device__ float g_dout_is[N_NODES];
__device__ float g_din_is [N_NODES];
__device__ float g_xw  [N_NODES * HID];    // GEMM0 output (feat @ W0)
__device__ float g_xsa [N_NODES * HID];    // dout-prescaled layer output (ping)
__device__ float g_xsb [N_NODES * HID];    // dout-prescaled layer output (pong)
__device__ float g_cat [N_NODES * CAT_F];  // JK concat of layer outputs
__device__ float g_y   [N_NODES * HID];    // cat @ W_mlp

// ---------------- small setup kernels ----------------
__global__ void k_zero() {
    int i = blockIdx.x * blockDim.x + threadIdx.x;
    if (i < N_NODES) { g_cnt_in[i] = 0; g_cnt_out[i] = 0; g_cursor[i] = 0; }
}

// single block, 1024 threads: exclusive scan of in-degrees -> CSR offsets,
// plus rsqrt of clipped degrees.
__global__ void k_scan() {
    __shared__ int part[1024];
    const int CH = (N_NODES + 1023) / 1024;  // 49
    int t = threadIdx.x;
    int beg = t * CH;
    int end = min(beg + CH, N_NODES);
    int s = 0;
    for (int i = beg; i < end; ++i) s += g_cnt_in[i];
    part[t] = s;
    __syncthreads();
    for (int d = 1; d < 1024; d <<= 1) {
        int v   = part[t];
        int add = (t >= d) ? part[t - d] : 0;
        __syncthreads();
        part[t] = v + add;
        __syncthreads();
    }
    int base = (t == 0) ? 0 : part[t - 1];
    for (int i = beg; i < end; ++i) {
        g_csr_off[i] = base;
        int cin = g_cnt_in[i];
        base += cin;
        g_din_is [i] = rsqrtf((float)max(cin, 1));
        g_dout_is[i] = rsqrtf((float)max(g_cnt_out[i], 1));
    }
    if (t == 1023) g_csr_off[N_NODES] = part[1023];
}

__global__ void k_bucket(const int* __restrict__ src, const int* __restrict__ dst) {
    int e = blockIdx.x * blockDim.x + threadIdx.x;
    if (e < N_EDGES) {
        int d = dst[e];
        int p = atomicAdd(&g_cursor[d], 1);
        g_esrc[g_csr_off[d] + p] = src[e];
    }
}

// ---------------- tf32 helpers ----------------
__device__ __forceinline__ uint32_t f2tf32(float f) {
    uint32_t r;
    asm("cvt.rna.tf32.f32 %0, %1;" : "=r"(r) : "f"(f));
    return r;
}

__device__ __forceinline__ void mma_tf32(float* d, const uint32_t* a, const uint32_t* b) {
    asm volatile(
        "mma.sync.aligned.m16n8k8.row.col.f32.tf32.tf32.f32 "
        "{%0,%1,%2,%3}, {%4,%5,%6,%7}, {%8,%9}, {%0,%1,%2,%3};"
        : "+f"(d[0]), "+f"(d[1]), "+f"(d[2]), "+f"(d[3])
        : "r"(a[0]), "r"(a[1]), "r"(a[2]), "r"(a[3]), "r"(b[0]), "r"(b[1]));
}

#define TC_LDS 20   // padded k-stride: conflict-free fragment gathers

// ---------------- big tensor-core GEMM (3xTF32): C[N,64] = A @ W ----------
// BM=128, BN=64, BK=16, 256 threads (8 warps = 4M x 2N).
__device__ __forceinline__ void gemm_tc_block(
    int bx,
    const float* __restrict__ A, int lda, int acol,
    const float* __restrict__ W, int K,
    float* __restrict__ C)
{
    __shared__ uint32_t As_hi[128 * TC_LDS];
    __shared__ uint32_t As_lo[128 * TC_LDS];
    __shared__ uint32_t Bs_hi[ 64 * TC_LDS];
    __shared__ uint32_t Bs_lo[ 64 * TC_LDS];

    const int M    = N_NODES;
    const int tid  = threadIdx.x;
    const int lane = tid & 31;
    const int warp = tid >> 5;
    const int gp   = lane >> 2;
    const int tg   = lane & 3;
    const int wm   = warp & 3;
    const int wn   = warp >> 2;
    const int m0   = bx * 128;

    float acc[2][4][4];
    #pragma unroll
    for (int mi = 0; mi < 2; ++mi)
        #pragma unroll
        for (int ni = 0; ni < 4; ++ni)
            #pragma unroll
            for (int j = 0; j < 4; ++j) acc[mi][ni][j] = 0.f;

    for (int kk = 0; kk < K; kk += 16) {
        #pragma unroll
        for (int q = 0; q < 2; ++q) {
            int f   = tid + 256 * q;
            int r   = f >> 2;
            int k4  = (f & 3) << 2;
            int row = m0 + r;
            float4 v = make_float4(0.f, 0.f, 0.f, 0.f);
            if (row < M)
                v = *(const float4*)&A[(size_t)row * lda + acol + kk + k4];
            uint32_t h0 = f2tf32(v.x), h1 = f2tf32(v.y), h2 = f2tf32(v.z), h3 = f2tf32(v.w);
            uint32_t l0 = f2tf32(v.x - __uint_as_float(h0));
            uint32_t l1 = f2tf32(v.y - __uint_as_float(h1));
            uint32_t l2 = f2tf32(v.z - __uint_as_float(h2));
            uint32_t l3 = f2tf32(v.w - __uint_as_float(h3));
            *(uint4*)&As_hi[r * TC_LDS + k4] = make_uint4(h0, h1, h2, h3);
            *(uint4*)&As_lo[r * TC_LDS + k4] = make_uint4(l0, l1, l2, l3);
        }
        {
            int n  = tid & 63;
            int kq = tid >> 6;
            uint32_t h[4], l[4];
            #pragma unroll
            for (int j = 0; j < 4; ++j) {
                float v = W[(size_t)(kk + kq * 4 + j) * 64 + n];
                h[j] = f2tf32(v);
                l[j] = f2tf32(v - __uint_as_float(h[j]));
            }
            *(uint4*)&Bs_hi[n * TC_LDS + kq * 4] = make_uint4(h[0], h[1], h[2], h[3]);
            *(uint4*)&Bs_lo[n * TC_LDS + kq * 4] = make_uint4(l[0], l[1], l[2], l[3]);
        }
        __syncthreads();

        #pragma unroll
        for (int k8 = 0; k8 < 16; k8 += 8) {
            uint32_t ah[2][4], al[2][4];
            #pragma unroll
            for (int mi = 0; mi < 2; ++mi) {
                int mb = wm * 32 + mi * 16;
                int i0 = (mb + gp)     * TC_LDS + k8 + tg;
                int i1 = (mb + gp + 8) * TC_LDS + k8 + tg;
                ah[mi][0] = As_hi[i0];     ah[mi][1] = As_hi[i1];
                ah[mi][2] = As_hi[i0 + 4]; ah[mi][3] = As_hi[i1 + 4];
                al[mi][0] = As_lo[i0];     al[mi][1] = As_lo[i1];
                al[mi][2] = As_lo[i0 + 4]; al[mi][3] = As_lo[i1 + 4];
            }
            #pragma unroll
            for (int ni = 0; ni < 4; ++ni) {
                int nb = wn * 32 + ni * 8;
                int j0 = (nb + gp) * TC_LDS + k8 + tg;
                uint32_t bh[2], bl[2];
                bh[0] = Bs_hi[j0]; bh[1] = Bs_hi[j0 + 4];
                bl[0] = Bs_lo[j0]; bl[1] = Bs_lo[j0 + 4];
                #pragma unroll
                for (int mi = 0; mi < 2; ++mi) {
                    mma_tf32(acc[mi][ni], ah[mi], bh);
                    mma_tf32(acc[mi][ni], al[mi], bh);
                    mma_tf32(acc[mi][ni], ah[mi], bl);
                }
            }
        }
        __syncthreads();
    }

    #pragma unroll
    for (int mi = 0; mi < 2; ++mi) {
        int rbase = m0 + wm * 32 + mi * 16 + gp;
        #pragma unroll
        for (int ni = 0; ni < 4; ++ni) {
            int col = wn * 32 + ni * 8 + 2 * tg;
            if (rbase < N_NODES)
                *(float2*)&C[(size_t)rbase * 64 + col] =
                    make_float2(acc[mi][ni][0], acc[mi][ni][1]);
            if (rbase + 8 < N_NODES)
                *(float2*)&C[(size_t)(rbase + 8) * 64 + col] =
                    make_float2(acc[mi][ni][2], acc[mi][ni][3]);
        }
    }
}

__global__ __launch_bounds__(256, 2) void k_gemm_tc(
    const float* __restrict__ A, int lda, int acol,
    const float* __restrict__ W, int K,
    float* __restrict__ C)
{
    gemm_tc_block(blockIdx.x, A, lda, acol, W, K, C);
}

// Fused: GEMM0 (feat @ W0) + degree counting in one launch.
__global__ __launch_bounds__(256, 2) void k_phase1(
    const float* __restrict__ feat, const float* __restrict__ W0,
    const int* __restrict__ src, const int* __restrict__ dst,
    int gemm_blocks, float* __restrict__ xw)
{
    if (blockIdx.x < (unsigned)gemm_blocks) {
        gemm_tc_block(blockIdx.x, feat, IN_F, 0, W0, IN_F, xw);
    } else {
        int e = (blockIdx.x - gemm_blocks) * 256 + threadIdx.x;
        if (e < N_EDGES) {
            atomicAdd(&g_cnt_out[src[e]], 1);
            atomicAdd(&g_cnt_in [dst[e]], 1);
        }
    }
}

// ---------------- fused hidden layer: aggregate(64 nodes) + GEMM64 ---------
// Using Agg(x@W) = Agg(x)@W:  h = relu( (din*Agg(xs_in)) @ W + b )
// xs_in is already dout-prescaled. Writes h to cat column block, and dout*h
// to xs_out for the next layer's aggregation.
__global__ __launch_bounds__(256) void k_layer_fused(
    const float* __restrict__ xs_in,    // [N, 64]
    const float* __restrict__ W,        // [64, 64]
    const float* __restrict__ bias,     // [64]
    float* __restrict__ cat_col,        // g_cat + layer*HID (row stride CAT_F)
    float* __restrict__ xs_out)         // [N, 64]
{
    __shared__ float    Zs[64][66];
    __shared__ uint32_t As_hi[64 * TC_LDS], As_lo[64 * TC_LDS];
    __shared__ uint32_t Bs_hi[64 * TC_LDS], Bs_lo[64 * TC_LDS];

    const int tid  = threadIdx.x;
    const int lane = tid & 31;
    const int warp = tid >> 5;
    const int m0   = blockIdx.x * 64;

    // ---- Phase A: aggregate 64 nodes into Zs (din-scaled) ----
    for (int w = warp; w < 64; w += 8) {
        int n = m0 + w;
        float2 acc = make_float2(0.f, 0.f);
        if (n < N_NODES) {
            int beg = g_csr_off[n];
            int end = g_csr_off[n + 1];
            int e = beg;
            for (; e + 4 <= end; e += 4) {
                int s0 = g_esrc[e + 0];
                int s1 = g_esrc[e + 1];
                int s2 = g_esrc[e + 2];
                int s3 = g_esrc[e + 3];
                float2 v0 = ((const float2*)(xs_in + (size_t)s0 * 64))[lane];
                float2 v1 = ((const float2*)(xs_in + (size_t)s1 * 64))[lane];
                float2 v2 = ((const float2*)(xs_in + (size_t)s2 * 64))[lane];
                float2 v3 = ((const float2*)(xs_in + (size_t)s3 * 64))[lane];
                acc.x += v0.x + v1.x + v2.x + v3.x;
                acc.y += v0.y + v1.y + v2.y + v3.y;
            }
            for (; e < end; ++e) {
                int s = g_esrc[e];
                float2 v = ((const float2*)(xs_in + (size_t)s * 64))[lane];
                acc.x += v.x; acc.y += v.y;
            }
            float sc = g_din_is[n];
            acc.x *= sc; acc.y *= sc;
        }
        Zs[w][2 * lane]     = acc.x;
        Zs[w][2 * lane + 1] = acc.y;
    }
    __syncthreads();

    // ---- Phase B: 64x64x64 GEMM from SMEM (3xTF32) ----
    const int gp = lane >> 2, tg = lane & 3;
    const int wm = warp & 1;       // 2 warps along M (32 rows each)
    const int wn = warp >> 1;      // 4 warps along N (16 cols each)

    float acc[2][2][4];
    #pragma unroll
    for (int mi = 0; mi < 2; ++mi)
        #pragma unroll
        for (int ni = 0; ni < 2; ++ni)
            #pragma unroll
            for (int j = 0; j < 4; ++j) acc[mi][ni][j] = 0.f;

    #pragma unroll
    for (int kk = 0; kk < 64; kk += 16) {
        // stage A chunk from Zs (64 rows x 16 cols), 4 threads per row
        {
            int r  = tid >> 2;
            int k4 = (tid & 3) << 2;
            float v0 = Zs[r][kk + k4 + 0];
            float v1 = Zs[r][kk + k4 + 1];
            float v2 = Zs[r][kk + k4 + 2];
            float v3 = Zs[r][kk + k4 + 3];
            uint32_t h0 = f2tf32(v0), h1 = f2tf32(v1), h2 = f2tf32(v2), h3 = f2tf32(v3);
            uint32_t l0 = f2tf32(v0 - __uint_as_float(h0));
            uint32_t l1 = f2tf32(v1 - __uint_as_float(h1));
            uint32_t l2 = f2tf32(v2 - __uint_as_float(h2));
            uint32_t l3 = f2tf32(v3 - __uint_as_float(h3));
            *(uint4*)&As_hi[r * TC_LDS + k4] = make_uint4(h0, h1, h2, h3);
            *(uint4*)&As_lo[r * TC_LDS + k4] = make_uint4(l0, l1, l2, l3);
        }
        // stage B chunk from W
        {
            int n  = tid & 63;
            int kq = tid >> 6;
            uint32_t h[4], l[4];
            #pragma unroll
            for (int j = 0; j < 4; ++j) {
                float v = W[(size_t)(kk + kq * 4 + j) * 64 + n];
                h[j] = f2tf32(v);
                l[j] = f2tf32(v - __uint_as_float(h[j]));
            }
            *(uint4*)&Bs_hi[n * TC_LDS + kq * 4] = make_uint4(h[0], h[1], h[2], h[3]);
            *(uint4*)&Bs_lo[n * TC_LDS + kq * 4] = make_uint4(l[0], l[1], l[2], l[3]);
        }
        __syncthreads();

        #pragma unroll
        for (int k8 = 0; k8 < 16; k8 += 8) {
            uint32_t ah[2][4], al[2][4];
            #pragma unroll
            for (int mi = 0; mi < 2; ++mi) {
                int mb = wm * 32 + mi * 16;
                int i0 = (mb + gp)     * TC_LDS + k8 + tg;
                int i1 = (mb + gp + 8) * TC_LDS + k8 + tg;
                ah[mi][0] = As_hi[i0];     ah[mi][1] = As_hi[i1];
                ah[mi][2] = As_hi[i0 + 4]; ah[mi][3] = As_hi[i1 + 4];
                al[mi][0] = As_lo[i0];     al[mi][1] = As_lo[i1];
                al[mi][2] = As_lo[i0 + 4]; al[mi][3] = As_lo[i1 + 4];
            }
            #pragma unroll
            for (int ni = 0; ni < 2; ++ni) {
                int nb = wn * 16 + ni * 8;
                int j0 = (nb + gp) * TC_LDS + k8 + tg;
                uint32_t bh[2], bl[2];
                bh[0] = Bs_hi[j0]; bh[1] = Bs_hi[j0 + 4];
                bl[0] = Bs_lo[j0]; bl[1] = Bs_lo[j0 + 4];
                #pragma unroll
                for (int mi = 0; mi < 2; ++mi) {
                    mma_tf32(acc[mi][ni], ah[mi], bh);
                    mma_tf32(acc[mi][ni], al[mi], bh);
                    mma_tf32(acc[mi][ni], ah[mi], bl);
                }
            }
        }
        __syncthreads();
    }

    // ---- epilogue: bias + relu -> cat, dout-prescaled -> xs_out ----
    #pragma unroll
    for (int mi = 0; mi < 2; ++mi) {
        int rbase = m0 + wm * 32 + mi * 16 + gp;
        #pragma unroll
        for (int ni = 0; ni < 2; ++ni) {
            int col = wn * 16 + ni * 8 + 2 * tg;
            float b0 = bias[col], b1 = bias[col + 1];
            #pragma unroll
            for (int half = 0; half < 2; ++half) {
                int row = rbase + half * 8;
                if (row < N_NODES) {
                    float h0 = fmaxf(acc[mi][ni][2 * half + 0] + b0, 0.f);
                    float h1 = fmaxf(acc[mi][ni][2 * half + 1] + b1, 0.f);
                    *(float2*)&cat_col[(size_t)row * CAT_F + col] = make_float2(h0, h1);
                    float ds = g_dout_is[row];
                    *(float2*)&xs_out[(size_t)row * 64 + col] = make_float2(ds * h0, ds * h1);
                }
            }
        }
    }
}

// ---------------- standalone CSR aggregation (layer 0 + final) -------------
template<bool EDGE_SCALE, bool DST_SCALE, bool RELU, bool WRITE_XS>
__global__ __launch_bounds__(256) void k_aggregate(
    const float* __restrict__ xin,          // [N, 64]
    float* __restrict__ out, int out_stride, int col_off,
    const float* __restrict__ bias,
    float* __restrict__ xs_out)             // used if WRITE_XS
{
    int gwarp = (blockIdx.x * blockDim.x + threadIdx.x) >> 5;
    int lane  = threadIdx.x & 31;
    if (gwarp >= N_NODES) return;

    int beg = g_csr_off[gwarp];
    int end = g_csr_off[gwarp + 1];

    float2 acc = make_float2(0.f, 0.f);
    int e = beg;
    for (; e + 4 <= end; e += 4) {
        int s0 = g_esrc[e + 0];
        int s1 = g_esrc[e + 1];
        int s2 = g_esrc[e + 2];
        int s3 = g_esrc[e + 3];
        float w0 = EDGE_SCALE ? g_dout_is[s0] : 1.f;
        float w1 = EDGE_SCALE ? g_dout_is[s1] : 1.f;
        float w2 = EDGE_SCALE ? g_dout_is[s2] : 1.f;
        float w3 = EDGE_SCALE ? g_dout_is[s3] : 1.f;
        float2 v0 = ((const float2*)(xin + (size_t)s0 * 64))[lane];
        float2 v1 = ((const float2*)(xin + (size_t)s1 * 64))[lane];
        float2 v2 = ((const float2*)(xin + (size_t)s2 * 64))[lane];
        float2 v3 = ((const float2*)(xin + (size_t)s3 * 64))[lane];
        if (EDGE_SCALE) {
            acc.x += w0 * v0.x + w1 * v1.x + w2 * v2.x + w3 * v3.x;
            acc.y += w0 * v0.y + w1 * v1.y + w2 * v2.y + w3 * v3.y;
        } else {
            acc.x += v0.x + v1.x + v2.x + v3.x;
            acc.y += v0.y + v1.y + v2.y + v3.y;
        }
    }
    for (; e < end; ++e) {
        int s = g_esrc[e];
        float2 v = ((const float2*)(xin + (size_t)s * 64))[lane];
        if (EDGE_SCALE) {
            float w = g_dout_is[s];
            acc.x += w * v.x; acc.y += w * v.y;
        } else {
            acc.x += v.x; acc.y += v.y;
        }
    }

    if (DST_SCALE) {
        float sc = g_din_is[gwarp];
        acc.x *= sc; acc.y *= sc;
    }
    float2 b2 = ((const float2*)bias)[lane];
    acc.x += b2.x; acc.y += b2.y;
    if (RELU) {
        acc.x = fmaxf(acc.x, 0.f);
        acc.y = fmaxf(acc.y, 0.f);
    }
    ((float2*)(out + (size_t)gwarp * out_stride + col_off))[lane] = acc;
    if (WRITE_XS) {
        float ds = g_dout_is[gwarp];
        ((float2*)(xs_out + (size_t)gwarp * 64))[lane] =
            make_float2(ds * acc.x, ds * acc.y);
    }
}

// ---------------- launch ----------------
extern "C" void kernel_launch(void* const* d_in, const int* in_sizes, int n_in,
                              void* d_out, int out_size)
{
    const float* feat  = (const float*)d_in[0];
    const int*   src   = (const int*)  d_in[1];
    const int*   dst   = (const int*)  d_in[2];
    const float* W[4]  = { (const float*)d_in[3], (const float*)d_in[5],
                           (const float*)d_in[7], (const float*)d_in[9] };
    const float* b[4]  = { (const float*)d_in[4], (const float*)d_in[6],
                           (const float*)d_in[8], (const float*)d_in[10] };
    const float* W_mlp = (const float*)d_in[11];
    const float* b_mlp = (const float*)d_in[12];
    float* out = (float*)d_out;

    float* xw;  cudaGetSymbolAddress((void**)&xw,  g_xw);
    float* xsa; cudaGetSymbolAddress((void**)&xsa, g_xsa);
    float* xsb; cudaGetSymbolAddress((void**)&xsb, g_xsb);
    float* cat; cudaGetSymbolAddress((void**)&cat, g_cat);
    float* y;   cudaGetSymbolAddress((void**)&y,   g_y);

    const int gemm_blocks  = (N_NODES + 127) / 128;   // 391
    const int fused_blocks = (N_NODES + 63) / 64;     // 782
    const int deg_blocks   = (N_EDGES + 255) / 256;   // 3125
    const int agg_blocks   = (N_NODES * 32 + 255) / 256;

    // --- CSR build; GEMM0 fused with degree counting ---
    k_zero  <<<(N_NODES + 255) / 256, 256>>>();
    k_phase1<<<gemm_blocks + deg_blocks, 256>>>(feat, W[0], src, dst, gemm_blocks, xw);
    k_scan  <<<1, 1024>>>();
    k_bucket<<<deg_blocks, 256>>>(src, dst);

    // --- layer 0: aggregate xw (edge-scaled), relu -> cat[:,0:64], prescaled -> xsa
    k_aggregate<true, true, true, true><<<agg_blocks, 256>>>(
        xw, cat, CAT_F, 0, b[0], xsa);

    // --- layers 1..3: fused aggregate + 64x64 GEMM ---
    k_layer_fused<<<fused_blocks, 256>>>(xsa, W[1], b[1], cat + 1 * HID, xsb);
    k_layer_fused<<<fused_blocks, 256>>>(xsb, W[2], b[2], cat + 2 * HID, xsa);
    k_layer_fused<<<fused_blocks, 256>>>(xsa, W[3], b[3], cat + 3 * HID, xsb);

    // --- final: y = cat @ W_mlp (K=256), then plain aggregate + b_mlp ---
    k_gemm_tc<<<gemm_blocks, 256>>>(cat, CAT_F, 0, W_mlp, CAT_F, y);
    k_aggregate<false, false, false, false><<<agg_blocks, 256>>>(
        y, out, HID, 0, b_mlp, (float*)nullptr);
}

// round 7
// speedup vs baseline: 1.1464x; 1.1464x over previous
#include <cuda_runtime.h>
#include <cuda_bf16.h>
#include <math.h>
#include <stdint.h>

#define N_NODES 50000
#define N_EDGES 800000
#define IN_F    256
#define HID     64
#define CAT_F   256   // 4 * HID

// ---------------- static scratch (no allocations allowed) ----------------
__device__ int   g_cnt_in [N_NODES];
__device__ int   g_cnt_out[N_NODES];
__device__ int   g_cursor [N_NODES];
__device__ int   g_csr_off[N_NODES + 1];
__device__ int   g_esrc   [N_EDGES];
__device__ float g_dout_is[N_NODES];
__device__ float g_din_is [N_NODES];
__device__ float g_xw [N_NODES * HID];     // per-layer GEMM output
__device__ float g_cat[N_NODES * CAT_F];   // JK concat of layer outputs
__device__ float g_y  [N_NODES * HID];     // cat @ W_mlp

// ---------------- setup kernels ----------------
// single block, 1024 threads: exclusive scan of in-degrees -> CSR offsets,
// rsqrt of clipped degrees, and cursor zeroing for k_bucket.
__global__ void k_scan() {
    __shared__ int part[1024];
    const int CH = (N_NODES + 1023) / 1024;  // 49
    int t = threadIdx.x;
    int beg = t * CH;
    int end = min(beg + CH, N_NODES);
    int s = 0;
    for (int i = beg; i < end; ++i) s += g_cnt_in[i];
    part[t] = s;
    __syncthreads();
    for (int d = 1; d < 1024; d <<= 1) {
        int v   = part[t];
        int add = (t >= d) ? part[t - d] : 0;
        __syncthreads();
        part[t] = v + add;
        __syncthreads();
    }
    int base = (t == 0) ? 0 : part[t - 1];
    for (int i = beg; i < end; ++i) {
        g_csr_off[i] = base;
        int cin = g_cnt_in[i];
        base += cin;
        g_cursor [i] = 0;
        g_din_is [i] = rsqrtf((float)max(cin, 1));
        g_dout_is[i] = rsqrtf((float)max(g_cnt_out[i], 1));
    }
    if (t == 1023) g_csr_off[N_NODES] = part[1023];
}

__global__ void k_bucket(const int* __restrict__ src, const int* __restrict__ dst) {
    int e = blockIdx.x * blockDim.x + threadIdx.x;
    if (e < N_EDGES) {
        int d = dst[e];
        int p = atomicAdd(&g_cursor[d], 1);
        g_esrc[g_csr_off[d] + p] = src[e];
    }
}

// ---------------- bf16 split helpers ----------------
// v = hi + lo with hi, lo bf16 (~16 mantissa bits total).
__device__ __forceinline__ void split_bf16_pair(float x, float y,
                                                uint32_t& hi, uint32_t& lo) {
    __nv_bfloat16 hx = __float2bfloat16_rn(x);
    __nv_bfloat16 hy = __float2bfloat16_rn(y);
    __nv_bfloat16 lx = __float2bfloat16_rn(x - __bfloat162float(hx));
    __nv_bfloat16 ly = __float2bfloat16_rn(y - __bfloat162float(hy));
    __nv_bfloat162 h2 = __nv_bfloat162(hx, hy);
    __nv_bfloat162 l2 = __nv_bfloat162(lx, ly);
    hi = *(uint32_t*)&h2;
    lo = *(uint32_t*)&l2;
}

__device__ __forceinline__ void mma_bf16(float* d, const uint32_t* a, const uint32_t* b) {
    asm volatile(
        "mma.sync.aligned.m16n8k16.row.col.f32.bf16.bf16.f32 "
        "{%0,%1,%2,%3}, {%4,%5,%6,%7}, {%8,%9}, {%0,%1,%2,%3};"
        : "+f"(d[0]), "+f"(d[1]), "+f"(d[2]), "+f"(d[3])
        : "r"(a[0]), "r"(a[1]), "r"(a[2]), "r"(a[3]), "r"(b[0]), "r"(b[1]));
}

// Row layout (uint32 units, stride 20): [0..7] hi k-pairs 0..7, [8..15] lo, pad.
// Fragment gathers hit addr (gp*20 + tg + c), conflict-free across a warp.
#define BF_LDS 20

// ---------------- tensor-core GEMM (3xBF16): C[N,64] = A @ W ---------------
// BM=128, BN=64, BK=16, 256 threads (8 warps = 4M x 2N), per-warp 32x32.
__device__ __forceinline__ void gemm_bf16_block(
    int bx,
    const float* __restrict__ A, int lda, int acol,
    const float* __restrict__ W, int K,
    float* __restrict__ C)
{
    __shared__ uint32_t As[128 * BF_LDS];
    __shared__ uint32_t Bs[ 64 * BF_LDS];

    const int M    = N_NODES;
    const int tid  = threadIdx.x;
    const int lane = tid & 31;
    const int warp = tid >> 5;
    const int gp   = lane >> 2;   // 0..7
    const int tg   = lane & 3;    // 0..3
    const int wm   = warp & 3;    // 4 warps along M
    const int wn   = warp >> 2;   // 2 warps along N
    const int m0   = bx * 128;

    float acc[2][4][4];
    #pragma unroll
    for (int mi = 0; mi < 2; ++mi)
        #pragma unroll
        for (int ni = 0; ni < 4; ++ni)
            #pragma unroll
            for (int j = 0; j < 4; ++j) acc[mi][ni][j] = 0.f;

    for (int kk = 0; kk < K; kk += 16) {
        // ---- stage A tile [128 rows x 16 k]: thread -> (row, k8-half) ----
        {
            int r   = tid >> 1;          // 0..127
            int h8  = tid & 1;           // which 8-k half
            int row = m0 + r;
            float4 v0 = make_float4(0.f, 0.f, 0.f, 0.f);
            float4 v1 = v0;
            if (row < M) {
                const float* p = &A[(size_t)row * lda + acol + kk + h8 * 8];
                v0 = *(const float4*)(p);
                v1 = *(const float4*)(p + 4);
            }
            uint32_t h[4], l[4];
            split_bf16_pair(v0.x, v0.y, h[0], l[0]);
            split_bf16_pair(v0.z, v0.w, h[1], l[1]);
            split_bf16_pair(v1.x, v1.y, h[2], l[2]);
            split_bf16_pair(v1.z, v1.w, h[3], l[3]);
            *(uint4*)&As[r * BF_LDS + h8 * 4]     = make_uint4(h[0], h[1], h[2], h[3]);
            *(uint4*)&As[r * BF_LDS + h8 * 4 + 8] = make_uint4(l[0], l[1], l[2], l[3]);
        }
        // ---- stage B tile: W[kk..kk+16) x 64 -> Bs[n][kpair] ----
        {
            int n  = tid & 63;
            int kq = tid >> 6;           // 0..3 -> k group of 4
            float w0 = W[(size_t)(kk + kq * 4 + 0) * 64 + n];
            float w1 = W[(size_t)(kk + kq * 4 + 1) * 64 + n];
            float w2 = W[(size_t)(kk + kq * 4 + 2) * 64 + n];
            float w3 = W[(size_t)(kk + kq * 4 + 3) * 64 + n];
            uint32_t h0, l0, h1, l1;
            split_bf16_pair(w0, w1, h0, l0);
            split_bf16_pair(w2, w3, h1, l1);
            Bs[n * BF_LDS + kq * 2]         = h0;
            Bs[n * BF_LDS + kq * 2 + 1]     = h1;
            Bs[n * BF_LDS + kq * 2 + 8]     = l0;
            Bs[n * BF_LDS + kq * 2 + 8 + 1] = l1;
        }
        __syncthreads();

        // ---- compute: one k16 step ----
        uint32_t ah[2][4], al[2][4];
        #pragma unroll
        for (int mi = 0; mi < 2; ++mi) {
            int b0 = (wm * 32 + mi * 16 + gp)     * BF_LDS;
            int b1 = (wm * 32 + mi * 16 + gp + 8) * BF_LDS;
            ah[mi][0] = As[b0 + tg];     ah[mi][1] = As[b1 + tg];
            ah[mi][2] = As[b0 + 4 + tg]; ah[mi][3] = As[b1 + 4 + tg];
            al[mi][0] = As[b0 + 8 + tg];     al[mi][1] = As[b1 + 8 + tg];
            al[mi][2] = As[b0 + 12 + tg];    al[mi][3] = As[b1 + 12 + tg];
        }
        #pragma unroll
        for (int ni = 0; ni < 4; ++ni) {
            int bb = (wn * 32 + ni * 8 + gp) * BF_LDS;
            uint32_t bh[2], bl[2];
            bh[0] = Bs[bb + tg]; bh[1] = Bs[bb + 4 + tg];
            bl[0] = Bs[bb + 8 + tg]; bl[1] = Bs[bb + 12 + tg];
            #pragma unroll
            for (int mi = 0; mi < 2; ++mi) {
                mma_bf16(acc[mi][ni], ah[mi], bh);
                mma_bf16(acc[mi][ni], al[mi], bh);
                mma_bf16(acc[mi][ni], ah[mi], bl);
            }
        }
        __syncthreads();
    }

    // ---- epilogue ----
    #pragma unroll
    for (int mi = 0; mi < 2; ++mi) {
        int rbase = m0 + wm * 32 + mi * 16 + gp;
        #pragma unroll
        for (int ni = 0; ni < 4; ++ni) {
            int col = wn * 32 + ni * 8 + 2 * tg;
            if (rbase < N_NODES)
                *(float2*)&C[(size_t)rbase * 64 + col] =
                    make_float2(acc[mi][ni][0], acc[mi][ni][1]);
            if (rbase + 8 < N_NODES)
                *(float2*)&C[(size_t)(rbase + 8) * 64 + col] =
                    make_float2(acc[mi][ni][2], acc[mi][ni][3]);
        }
    }
}

__global__ __launch_bounds__(256, 2) void k_gemm_tc(
    const float* __restrict__ A, int lda, int acol,
    const float* __restrict__ W, int K,
    float* __restrict__ C)
{
    gemm_bf16_block(blockIdx.x, A, lda, acol, W, K, C);
}

// Fused: GEMM0 (feat @ W0, unscaled) + degree counting in one launch.
__global__ __launch_bounds__(256, 2) void k_phase1(
    const float* __restrict__ feat, const float* __restrict__ W0,
    const int* __restrict__ src, const int* __restrict__ dst,
    int gemm_blocks, float* __restrict__ xw)
{
    if (blockIdx.x < (unsigned)gemm_blocks) {
        gemm_bf16_block(blockIdx.x, feat, IN_F, 0, W0, IN_F, xw);
    } else {
        int e = (blockIdx.x - gemm_blocks) * 256 + threadIdx.x;
        if (e < N_EDGES) {
            atomicAdd(&g_cnt_out[src[e]], 1);
            atomicAdd(&g_cnt_in [dst[e]], 1);
        }
    }
}

// ---------------- CSR aggregation: one warp per node, 64 features ----------
// out[n, col_off+f] = act( din_is[n]? * sum_e dout_is[src_e]? * xin[src_e, f] + bias[f] )
template<bool EDGE_SCALE, bool DST_SCALE, bool RELU>
__global__ __launch_bounds__(256) void k_aggregate(
    const float* __restrict__ xin,          // [N, 64]
    float* __restrict__ out, int out_stride, int col_off,
    const float* __restrict__ bias)
{
    int gwarp = (blockIdx.x * blockDim.x + threadIdx.x) >> 5;
    int lane  = threadIdx.x & 31;
    if (gwarp >= N_NODES) return;

    int beg = g_csr_off[gwarp];
    int end = g_csr_off[gwarp + 1];

    float2 acc = make_float2(0.f, 0.f);
    int e = beg;
    for (; e + 4 <= end; e += 4) {
        int s0 = g_esrc[e + 0];
        int s1 = g_esrc[e + 1];
        int s2 = g_esrc[e + 2];
        int s3 = g_esrc[e + 3];
        float w0 = EDGE_SCALE ? g_dout_is[s0] : 1.f;
        float w1 = EDGE_SCALE ? g_dout_is[s1] : 1.f;
        float w2 = EDGE_SCALE ? g_dout_is[s2] : 1.f;
        float w3 = EDGE_SCALE ? g_dout_is[s3] : 1.f;
        float2 v0 = ((const float2*)(xin + (size_t)s0 * 64))[lane];
        float2 v1 = ((const float2*)(xin + (size_t)s1 * 64))[lane];
        float2 v2 = ((const float2*)(xin + (size_t)s2 * 64))[lane];
        float2 v3 = ((const float2*)(xin + (size_t)s3 * 64))[lane];
        if (EDGE_SCALE) {
            acc.x += w0 * v0.x + w1 * v1.x + w2 * v2.x + w3 * v3.x;
            acc.y += w0 * v0.y + w1 * v1.y + w2 * v2.y + w3 * v3.y;
        } else {
            acc.x += v0.x + v1.x + v2.x + v3.x;
            acc.y += v0.y + v1.y + v2.y + v3.y;
        }
    }
    for (; e < end; ++e) {
        int s = g_esrc[e];
        float2 v = ((const float2*)(xin + (size_t)s * 64))[lane];
        if (EDGE_SCALE) {
            float w = g_dout_is[s];
            acc.x += w * v.x; acc.y += w * v.y;
        } else {
            acc.x += v.x; acc.y += v.y;
        }
    }

    if (DST_SCALE) {
        float sc = g_din_is[gwarp];
        acc.x *= sc; acc.y *= sc;
    }
    float2 b2 = ((const float2*)bias)[lane];
    acc.x += b2.x; acc.y += b2.y;
    if (RELU) {
        acc.x = fmaxf(acc.x, 0.f);
        acc.y = fmaxf(acc.y, 0.f);
    }
    ((float2*)(out + (size_t)gwarp * out_stride + col_off))[lane] = acc;
}

// ---------------- launch ----------------
extern "C" void kernel_launch(void* const* d_in, const int* in_sizes, int n_in,
                              void* d_out, int out_size)
{
    const float* feat  = (const float*)d_in[0];
    const int*   src   = (const int*)  d_in[1];
    const int*   dst   = (const int*)  d_in[2];
    const float* W[4]  = { (const float*)d_in[3], (const float*)d_in[5],
                           (const float*)d_in[7], (const float*)d_in[9] };
    const float* b[4]  = { (const float*)d_in[4], (const float*)d_in[6],
                           (const float*)d_in[8], (const float*)d_in[10] };
    const float* W_mlp = (const float*)d_in[11];
    const float* b_mlp = (const float*)d_in[12];
    float* out = (float*)d_out;

    float* xw;  cudaGetSymbolAddress((void**)&xw,  g_xw);
    float* cat; cudaGetSymbolAddress((void**)&cat, g_cat);
    float* y;   cudaGetSymbolAddress((void**)&y,   g_y);
    int* cnt_in;  cudaGetSymbolAddress((void**)&cnt_in,  g_cnt_in);
    int* cnt_out; cudaGetSymbolAddress((void**)&cnt_out, g_cnt_out);

    const int gemm_blocks = (N_NODES + 127) / 128;           // 391
    const int deg_blocks  = (N_EDGES + 255) / 256;           // 3125
    const int agg_blocks  = (N_NODES * 32 + 255) / 256;

    // --- CSR build; zeroing via memset nodes (not kernel launches) ---
    cudaMemsetAsync(cnt_in,  0, N_NODES * sizeof(int));
    cudaMemsetAsync(cnt_out, 0, N_NODES * sizeof(int));
    k_phase1<<<gemm_blocks + deg_blocks, 256>>>(feat, W[0], src, dst, gemm_blocks, xw);
    k_scan  <<<1, 1024>>>();                                  // also zeroes cursors
    k_bucket<<<deg_blocks, 256>>>(src, dst);

    // --- 4 GCN layers (edge-side dout scaling inside aggregate) ---
    k_aggregate<true, true, true><<<agg_blocks, 256>>>(xw, cat, CAT_F, 0, b[0]);
    for (int i = 1; i < 4; ++i) {
        k_gemm_tc<<<gemm_blocks, 256>>>(cat, CAT_F, (i - 1) * HID, W[i], HID, xw);
        k_aggregate<true, true, true><<<agg_blocks, 256>>>(xw, cat, CAT_F, i * HID, b[i]);
    }

    // --- final: y = cat @ W_mlp, then out = segment_sum(y[src], dst) + b_mlp ---
    k_gemm_tc<<<gemm_blocks, 256>>>(cat, CAT_F, 0, W_mlp, CAT_F, y);
    k_aggregate<false, false, false><<<agg_blocks, 256>>>(y, out, HID, 0, b_mlp);
}

// round 8
// speedup vs baseline: 1.1512x; 1.0043x over previous
#include <cuda_runtime.h>
#include <cuda_bf16.h>
#include <math.h>
#include <stdint.h>

#define N_NODES 50000
#define N_EDGES 800000
#define IN_F    256
#define HID     64
#define CAT_F   256   // 4 * HID

// ---------------- static scratch (no allocations allowed) ----------------
__device__ int   g_cnt_in [N_NODES];
__device__ int   g_cnt_out[N_NODES];
__device__ int   g_cursor [N_NODES];
__device__ int   g_csr_off[N_NODES + 1];
__device__ int   g_esrc   [N_EDGES];
__device__ float g_dout_is[N_NODES];
__device__ float g_din_is [N_NODES];
__device__ float g_xs [N_NODES * HID];     // dout-prescaled GEMM output
__device__ float g_cat[N_NODES * CAT_F];   // JK concat of layer outputs
__device__ float g_y  [N_NODES * HID];     // cat @ W_mlp

// ---------------- setup kernels ----------------
__global__ void k_degree(const int* __restrict__ src, const int* __restrict__ dst) {
    int e = blockIdx.x * blockDim.x + threadIdx.x;
    if (e < N_EDGES) {
        atomicAdd(&g_cnt_out[src[e]], 1);
        atomicAdd(&g_cnt_in [dst[e]], 1);
    }
}

// single block, 1024 threads: exclusive scan of in-degrees -> CSR offsets,
// rsqrt of clipped degrees, and cursor zeroing for k_bucket.
__global__ void k_scan() {
    __shared__ int part[1024];
    const int CH = (N_NODES + 1023) / 1024;  // 49
    int t = threadIdx.x;
    int beg = t * CH;
    int end = min(beg + CH, N_NODES);
    int s = 0;
    for (int i = beg; i < end; ++i) s += g_cnt_in[i];
    part[t] = s;
    __syncthreads();
    for (int d = 1; d < 1024; d <<= 1) {
        int v   = part[t];
        int add = (t >= d) ? part[t - d] : 0;
        __syncthreads();
        part[t] = v + add;
        __syncthreads();
    }
    int base = (t == 0) ? 0 : part[t - 1];
    for (int i = beg; i < end; ++i) {
        g_csr_off[i] = base;
        int cin = g_cnt_in[i];
        base += cin;
        g_cursor [i] = 0;
        g_din_is [i] = rsqrtf((float)max(cin, 1));
        g_dout_is[i] = rsqrtf((float)max(g_cnt_out[i], 1));
    }
    if (t == 1023) g_csr_off[N_NODES] = part[1023];
}

// ---------------- bf16 split helpers ----------------
__device__ __forceinline__ void split_bf16_pair(float x, float y,
                                                uint32_t& hi, uint32_t& lo) {
    __nv_bfloat16 hx = __float2bfloat16_rn(x);
    __nv_bfloat16 hy = __float2bfloat16_rn(y);
    __nv_bfloat16 lx = __float2bfloat16_rn(x - __bfloat162float(hx));
    __nv_bfloat16 ly = __float2bfloat16_rn(y - __bfloat162float(hy));
    __nv_bfloat162 h2 = __nv_bfloat162(hx, hy);
    __nv_bfloat162 l2 = __nv_bfloat162(lx, ly);
    hi = *(uint32_t*)&h2;
    lo = *(uint32_t*)&l2;
}

__device__ __forceinline__ void mma_bf16(float* d, const uint32_t* a, const uint32_t* b) {
    asm volatile(
        "mma.sync.aligned.m16n8k16.row.col.f32.bf16.bf16.f32 "
        "{%0,%1,%2,%3}, {%4,%5,%6,%7}, {%8,%9}, {%0,%1,%2,%3};"
        : "+f"(d[0]), "+f"(d[1]), "+f"(d[2]), "+f"(d[3])
        : "r"(a[0]), "r"(a[1]), "r"(a[2]), "r"(a[3]), "r"(b[0]), "r"(b[1]));
}

#define BF_LDS 20

// ---------------- tensor-core GEMM (3xBF16): C[N,64] = A @ W ---------------
// BM=128, BN=64, BK=16, 256 threads (8 warps = 4M x 2N), per-warp 32x32.
// SCALE_OUT: multiply each output row by g_dout_is[row] before storing.
template<bool SCALE_OUT>
__device__ __forceinline__ void gemm_bf16_block(
    int bx,
    const float* __restrict__ A, int lda, int acol,
    const float* __restrict__ W, int K,
    float* __restrict__ C)
{
    __shared__ uint32_t As[128 * BF_LDS];
    __shared__ uint32_t Bs[ 64 * BF_LDS];

    const int M    = N_NODES;
    const int tid  = threadIdx.x;
    const int lane = tid & 31;
    const int warp = tid >> 5;
    const int gp   = lane >> 2;
    const int tg   = lane & 3;
    const int wm   = warp & 3;
    const int wn   = warp >> 2;
    const int m0   = bx * 128;

    float acc[2][4][4];
    #pragma unroll
    for (int mi = 0; mi < 2; ++mi)
        #pragma unroll
        for (int ni = 0; ni < 4; ++ni)
            #pragma unroll
            for (int j = 0; j < 4; ++j) acc[mi][ni][j] = 0.f;

    for (int kk = 0; kk < K; kk += 16) {
        {
            int r   = tid >> 1;
            int h8  = tid & 1;
            int row = m0 + r;
            float4 v0 = make_float4(0.f, 0.f, 0.f, 0.f);
            float4 v1 = v0;
            if (row < M) {
                const float* p = &A[(size_t)row * lda + acol + kk + h8 * 8];
                v0 = *(const float4*)(p);
                v1 = *(const float4*)(p + 4);
            }
            uint32_t h[4], l[4];
            split_bf16_pair(v0.x, v0.y, h[0], l[0]);
            split_bf16_pair(v0.z, v0.w, h[1], l[1]);
            split_bf16_pair(v1.x, v1.y, h[2], l[2]);
            split_bf16_pair(v1.z, v1.w, h[3], l[3]);
            *(uint4*)&As[r * BF_LDS + h8 * 4]     = make_uint4(h[0], h[1], h[2], h[3]);
            *(uint4*)&As[r * BF_LDS + h8 * 4 + 8] = make_uint4(l[0], l[1], l[2], l[3]);
        }
        {
            int n  = tid & 63;
            int kq = tid >> 6;
            float w0 = W[(size_t)(kk + kq * 4 + 0) * 64 + n];
            float w1 = W[(size_t)(kk + kq * 4 + 1) * 64 + n];
            float w2 = W[(size_t)(kk + kq * 4 + 2) * 64 + n];
            float w3 = W[(size_t)(kk + kq * 4 + 3) * 64 + n];
            uint32_t h0, l0, h1, l1;
            split_bf16_pair(w0, w1, h0, l0);
            split_bf16_pair(w2, w3, h1, l1);
            Bs[n * BF_LDS + kq * 2]         = h0;
            Bs[n * BF_LDS + kq * 2 + 1]     = h1;
            Bs[n * BF_LDS + kq * 2 + 8]     = l0;
            Bs[n * BF_LDS + kq * 2 + 8 + 1] = l1;
        }
        __syncthreads();

        uint32_t ah[2][4], al[2][4];
        #pragma unroll
        for (int mi = 0; mi < 2; ++mi) {
            int b0 = (wm * 32 + mi * 16 + gp)     * BF_LDS;
            int b1 = (wm * 32 + mi * 16 + gp + 8) * BF_LDS;
            ah[mi][0] = As[b0 + tg];     ah[mi][1] = As[b1 + tg];
            ah[mi][2] = As[b0 + 4 + tg]; ah[mi][3] = As[b1 + 4 + tg];
            al[mi][0] = As[b0 + 8 + tg];     al[mi][1] = As[b1 + 8 + tg];
            al[mi][2] = As[b0 + 12 + tg];    al[mi][3] = As[b1 + 12 + tg];
        }
        #pragma unroll
        for (int ni = 0; ni < 4; ++ni) {
            int bb = (wn * 32 + ni * 8 + gp) * BF_LDS;
            uint32_t bh[2], bl[2];
            bh[0] = Bs[bb + tg]; bh[1] = Bs[bb + 4 + tg];
            bl[0] = Bs[bb + 8 + tg]; bl[1] = Bs[bb + 12 + tg];
            #pragma unroll
            for (int mi = 0; mi < 2; ++mi) {
                mma_bf16(acc[mi][ni], ah[mi], bh);
                mma_bf16(acc[mi][ni], al[mi], bh);
                mma_bf16(acc[mi][ni], ah[mi], bl);
            }
        }
        __syncthreads();
    }

    #pragma unroll
    for (int mi = 0; mi < 2; ++mi) {
        int rbase = m0 + wm * 32 + mi * 16 + gp;
        float s0 = 1.f, s1 = 1.f;
        if (SCALE_OUT) {
            if (rbase < N_NODES)     s0 = g_dout_is[rbase];
            if (rbase + 8 < N_NODES) s1 = g_dout_is[rbase + 8];
        }
        #pragma unroll
        for (int ni = 0; ni < 4; ++ni) {
            int col = wn * 32 + ni * 8 + 2 * tg;
            if (rbase < N_NODES)
                *(float2*)&C[(size_t)rbase * 64 + col] =
                    make_float2(s0 * acc[mi][ni][0], s0 * acc[mi][ni][1]);
            if (rbase + 8 < N_NODES)
                *(float2*)&C[(size_t)(rbase + 8) * 64 + col] =
                    make_float2(s1 * acc[mi][ni][2], s1 * acc[mi][ni][3]);
        }
    }
}

template<bool SCALE_OUT>
__global__ __launch_bounds__(256, 2) void k_gemm_tc(
    const float* __restrict__ A, int lda, int acol,
    const float* __restrict__ W, int K,
    float* __restrict__ C)
{
    gemm_bf16_block<SCALE_OUT>(blockIdx.x, A, lda, acol, W, K, C);
}

// Fused: GEMM0 (dout * (feat @ W0)) + CSR bucketing; both depend only on k_scan.
__global__ __launch_bounds__(256, 2) void k_phase2(
    const float* __restrict__ feat, const float* __restrict__ W0,
    const int* __restrict__ src, const int* __restrict__ dst,
    int gemm_blocks, float* __restrict__ xs)
{
    if (blockIdx.x < (unsigned)gemm_blocks) {
        gemm_bf16_block<true>(blockIdx.x, feat, IN_F, 0, W0, IN_F, xs);
    } else {
        int e = (blockIdx.x - gemm_blocks) * 256 + threadIdx.x;
        if (e < N_EDGES) {
            int d = dst[e];
            int p = atomicAdd(&g_cursor[d], 1);
            g_esrc[g_csr_off[d] + p] = src[e];
        }
    }
}

// ---------------- CSR aggregation: one warp per node, 64 features ----------
// out[n, col_off+f] = act( din_is[n]? * sum_e xin[src_e, f] + bias[f] )
// Index loads: int4 (lane-uniform LDG.128) after peeling to 4-alignment.
template<bool DST_SCALE, bool RELU>
__global__ __launch_bounds__(256) void k_aggregate(
    const float* __restrict__ xin,          // [N, 64] (already dout-prescaled)
    float* __restrict__ out, int out_stride, int col_off,
    const float* __restrict__ bias)
{
    int gwarp = (blockIdx.x * blockDim.x + threadIdx.x) >> 5;
    int lane  = threadIdx.x & 31;
    if (gwarp >= N_NODES) return;

    int beg = g_csr_off[gwarp];
    int end = g_csr_off[gwarp + 1];

    float2 acc = make_float2(0.f, 0.f);
    int e = beg;
    // peel to 4-edge alignment (g_esrc is 16B-aligned at indices %4==0)
    while (e < end && (e & 3)) {
        int s = g_esrc[e++];
        float2 v = ((const float2*)(xin + (size_t)s * 64))[lane];
        acc.x += v.x; acc.y += v.y;
    }
    for (; e + 4 <= end; e += 4) {
        int4 s4 = *(const int4*)&g_esrc[e];
        float2 v0 = ((const float2*)(xin + (size_t)s4.x * 64))[lane];
        float2 v1 = ((const float2*)(xin + (size_t)s4.y * 64))[lane];
        float2 v2 = ((const float2*)(xin + (size_t)s4.z * 64))[lane];
        float2 v3 = ((const float2*)(xin + (size_t)s4.w * 64))[lane];
        acc.x += v0.x + v1.x + v2.x + v3.x;
        acc.y += v0.y + v1.y + v2.y + v3.y;
    }
    for (; e < end; ++e) {
        int s = g_esrc[e];
        float2 v = ((const float2*)(xin + (size_t)s * 64))[lane];
        acc.x += v.x; acc.y += v.y;
    }

    if (DST_SCALE) {
        float sc = g_din_is[gwarp];
        acc.x *= sc; acc.y *= sc;
    }
    float2 b2 = ((const float2*)bias)[lane];
    acc.x += b2.x; acc.y += b2.y;
    if (RELU) {
        acc.x = fmaxf(acc.x, 0.f);
        acc.y = fmaxf(acc.y, 0.f);
    }
    ((float2*)(out + (size_t)gwarp * out_stride + col_off))[lane] = acc;
}

// ---------------- launch ----------------
extern "C" void kernel_launch(void* const* d_in, const int* in_sizes, int n_in,
                              void* d_out, int out_size)
{
    const float* feat  = (const float*)d_in[0];
    const int*   src   = (const int*)  d_in[1];
    const int*   dst   = (const int*)  d_in[2];
    const float* W[4]  = { (const float*)d_in[3], (const float*)d_in[5],
                           (const float*)d_in[7], (const float*)d_in[9] };
    const float* b[4]  = { (const float*)d_in[4], (const float*)d_in[6],
                           (const float*)d_in[8], (const float*)d_in[10] };
    const float* W_mlp = (const float*)d_in[11];
    const float* b_mlp = (const float*)d_in[12];
    float* out = (float*)d_out;

    float* xs;  cudaGetSymbolAddress((void**)&xs,  g_xs);
    float* cat; cudaGetSymbolAddress((void**)&cat, g_cat);
    float* y;   cudaGetSymbolAddress((void**)&y,   g_y);
    int* cnt_in;  cudaGetSymbolAddress((void**)&cnt_in,  g_cnt_in);
    int* cnt_out; cudaGetSymbolAddress((void**)&cnt_out, g_cnt_out);

    const int gemm_blocks = (N_NODES + 127) / 128;           // 391
    const int deg_blocks  = (N_EDGES + 255) / 256;           // 3125
    const int agg_blocks  = (N_NODES * 32 + 255) / 256;

    // --- CSR build; GEMM0 (dout-prescaled epilogue) fused with bucketing ---
    cudaMemsetAsync(cnt_in,  0, N_NODES * sizeof(int));
    cudaMemsetAsync(cnt_out, 0, N_NODES * sizeof(int));
    k_degree<<<deg_blocks, 256>>>(src, dst);
    k_scan  <<<1, 1024>>>();                                  // offsets + rsqrts + cursors
    k_phase2<<<gemm_blocks + deg_blocks, 256>>>(feat, W[0], src, dst, gemm_blocks, xs);

    // --- 4 GCN layers: all aggregates are scale-free gathers of prescaled xs ---
    k_aggregate<true, true><<<agg_blocks, 256>>>(xs, cat, CAT_F, 0, b[0]);
    for (int i = 1; i < 4; ++i) {
        k_gemm_tc<true><<<gemm_blocks, 256>>>(cat, CAT_F, (i - 1) * HID, W[i], HID, xs);
        k_aggregate<true, true><<<agg_blocks, 256>>>(xs, cat, CAT_F, i * HID, b[i]);
    }

    // --- final: y = cat @ W_mlp (unscaled), then plain aggregate + b_mlp ---
    k_gemm_tc<false><<<gemm_blocks, 256>>>(cat, CAT_F, 0, W_mlp, CAT_F, y);
    k_aggregate<false, false><<<agg_blocks, 256>>>(y, out, HID, 0, b_mlp);
}

// round 9
// speedup vs baseline: 1.1652x; 1.0121x over previous
#include <cuda_runtime.h>
#include <cuda_bf16.h>
#include <math.h>
#include <stdint.h>

#define N_NODES 50000
#define N_EDGES 800000
#define IN_F    256
#define HID     64
#define CAT_F   256   // 4 * HID

// ---------------- static scratch (no allocations allowed) ----------------
__device__ int   g_cnt_in [N_NODES];
__device__ int   g_cnt_out[N_NODES];
__device__ int   g_cursor [N_NODES];
__device__ int   g_csr_off[N_NODES + 1];
__device__ int   g_esrc   [N_EDGES];
__device__ float g_dout_is[N_NODES];
__device__ float g_din_is [N_NODES];
__device__ float g_xs [N_NODES * HID];     // dout-prescaled GEMM output
__device__ float g_cat[N_NODES * CAT_F];   // JK concat of layer outputs
__device__ float g_y  [N_NODES * HID];     // cat @ W_mlp

// ---------------- setup kernels ----------------
__global__ void k_degree(const int* __restrict__ src, const int* __restrict__ dst) {
    int e = blockIdx.x * blockDim.x + threadIdx.x;
    if (e < N_EDGES) {
        atomicAdd(&g_cnt_out[src[e]], 1);
        atomicAdd(&g_cnt_in [dst[e]], 1);
    }
}

// single block, 1024 threads: exclusive scan of in-degrees -> CSR offsets,
// rsqrt of clipped degrees, and cursor zeroing for bucketing.
__global__ void k_scan() {
    __shared__ int part[1024];
    const int CH = 52;                       // multiple of 4 for int4 loads
    int t = threadIdx.x;
    int beg = t * CH;
    int end = min(beg + CH, N_NODES);
    int s = 0;
    if (beg < N_NODES) {
        int i = beg;
        for (; i + 4 <= end; i += 4) {
            int4 c4 = *(const int4*)&g_cnt_in[i];
            s += c4.x + c4.y + c4.z + c4.w;
        }
        for (; i < end; ++i) s += g_cnt_in[i];
    }
    part[t] = s;
    __syncthreads();
    for (int d = 1; d < 1024; d <<= 1) {
        int v   = part[t];
        int add = (t >= d) ? part[t - d] : 0;
        __syncthreads();
        part[t] = v + add;
        __syncthreads();
    }
    int base = (t == 0) ? 0 : part[t - 1];
    for (int i = beg; i < end; ++i) {
        g_csr_off[i] = base;
        int cin = g_cnt_in[i];
        base += cin;
        g_cursor [i] = 0;
        g_din_is [i] = rsqrtf((float)max(cin, 1));
        g_dout_is[i] = rsqrtf((float)max(g_cnt_out[i], 1));
    }
    if (t == 1023) g_csr_off[N_NODES] = part[1023];
}

// ---------------- bf16 split helpers ----------------
__device__ __forceinline__ void split_bf16_pair(float x, float y,
                                                uint32_t& hi, uint32_t& lo) {
    __nv_bfloat16 hx = __float2bfloat16_rn(x);
    __nv_bfloat16 hy = __float2bfloat16_rn(y);
    __nv_bfloat16 lx = __float2bfloat16_rn(x - __bfloat162float(hx));
    __nv_bfloat16 ly = __float2bfloat16_rn(y - __bfloat162float(hy));
    __nv_bfloat162 h2 = __nv_bfloat162(hx, hy);
    __nv_bfloat162 l2 = __nv_bfloat162(lx, ly);
    hi = *(uint32_t*)&h2;
    lo = *(uint32_t*)&l2;
}

__device__ __forceinline__ void mma_bf16(float* d, const uint32_t* a, const uint32_t* b) {
    asm volatile(
        "mma.sync.aligned.m16n8k16.row.col.f32.bf16.bf16.f32 "
        "{%0,%1,%2,%3}, {%4,%5,%6,%7}, {%8,%9}, {%0,%1,%2,%3};"
        : "+f"(d[0]), "+f"(d[1]), "+f"(d[2]), "+f"(d[3])
        : "r"(a[0]), "r"(a[1]), "r"(a[2]), "r"(a[3]), "r"(b[0]), "r"(b[1]));
}

#define BF_LDS 20

// ---------------- tensor-core GEMM (3xBF16): C[N,64] = A @ W ---------------
// BM=128, BN=64, BK=16, 256 threads (8 warps = 4M x 2N), per-warp 32x32.
// SCALE_OUT: multiply each output row by g_dout_is[row] before storing.
template<bool SCALE_OUT>
__device__ __forceinline__ void gemm_bf16_block(
    int bx,
    const float* __restrict__ A, int lda, int acol,
    const float* __restrict__ W, int K,
    float* __restrict__ C)
{
    __shared__ uint32_t As[128 * BF_LDS];
    __shared__ uint32_t Bs[ 64 * BF_LDS];

    const int M    = N_NODES;
    const int tid  = threadIdx.x;
    const int lane = tid & 31;
    const int warp = tid >> 5;
    const int gp   = lane >> 2;
    const int tg   = lane & 3;
    const int wm   = warp & 3;
    const int wn   = warp >> 2;
    const int m0   = bx * 128;

    float acc[2][4][4];
    #pragma unroll
    for (int mi = 0; mi < 2; ++mi)
        #pragma unroll
        for (int ni = 0; ni < 4; ++ni)
            #pragma unroll
            for (int j = 0; j < 4; ++j) acc[mi][ni][j] = 0.f;

    for (int kk = 0; kk < K; kk += 16) {
        {
            int r   = tid >> 1;
            int h8  = tid & 1;
            int row = m0 + r;
            float4 v0 = make_float4(0.f, 0.f, 0.f, 0.f);
            float4 v1 = v0;
            if (row < M) {
                const float* p = &A[(size_t)row * lda + acol + kk + h8 * 8];
                v0 = *(const float4*)(p);
                v1 = *(const float4*)(p + 4);
            }
            uint32_t h[4], l[4];
            split_bf16_pair(v0.x, v0.y, h[0], l[0]);
            split_bf16_pair(v0.z, v0.w, h[1], l[1]);
            split_bf16_pair(v1.x, v1.y, h[2], l[2]);
            split_bf16_pair(v1.z, v1.w, h[3], l[3]);
            *(uint4*)&As[r * BF_LDS + h8 * 4]     = make_uint4(h[0], h[1], h[2], h[3]);
            *(uint4*)&As[r * BF_LDS + h8 * 4 + 8] = make_uint4(l[0], l[1], l[2], l[3]);
        }
        {
            int n  = tid & 63;
            int kq = tid >> 6;
            float w0 = W[(size_t)(kk + kq * 4 + 0) * 64 + n];
            float w1 = W[(size_t)(kk + kq * 4 + 1) * 64 + n];
            float w2 = W[(size_t)(kk + kq * 4 + 2) * 64 + n];
            float w3 = W[(size_t)(kk + kq * 4 + 3) * 64 + n];
            uint32_t h0, l0, h1, l1;
            split_bf16_pair(w0, w1, h0, l0);
            split_bf16_pair(w2, w3, h1, l1);
            Bs[n * BF_LDS + kq * 2]         = h0;
            Bs[n * BF_LDS + kq * 2 + 1]     = h1;
            Bs[n * BF_LDS + kq * 2 + 8]     = l0;
            Bs[n * BF_LDS + kq * 2 + 8 + 1] = l1;
        }
        __syncthreads();

        uint32_t ah[2][4], al[2][4];
        #pragma unroll
        for (int mi = 0; mi < 2; ++mi) {
            int b0 = (wm * 32 + mi * 16 + gp)     * BF_LDS;
            int b1 = (wm * 32 + mi * 16 + gp + 8) * BF_LDS;
            ah[mi][0] = As[b0 + tg];     ah[mi][1] = As[b1 + tg];
            ah[mi][2] = As[b0 + 4 + tg]; ah[mi][3] = As[b1 + 4 + tg];
            al[mi][0] = As[b0 + 8 + tg];     al[mi][1] = As[b1 + 8 + tg];
            al[mi][2] = As[b0 + 12 + tg];    al[mi][3] = As[b1 + 12 + tg];
        }
        #pragma unroll
        for (int ni = 0; ni < 4; ++ni) {
            int bb = (wn * 32 + ni * 8 + gp) * BF_LDS;
            uint32_t bh[2], bl[2];
            bh[0] = Bs[bb + tg]; bh[1] = Bs[bb + 4 + tg];
            bl[0] = Bs[bb + 8 + tg]; bl[1] = Bs[bb + 12 + tg];
            #pragma unroll
            for (int mi = 0; mi < 2; ++mi) {
                mma_bf16(acc[mi][ni], ah[mi], bh);
                mma_bf16(acc[mi][ni], al[mi], bh);
                mma_bf16(acc[mi][ni], ah[mi], bl);
            }
        }
        __syncthreads();
    }

    #pragma unroll
    for (int mi = 0; mi < 2; ++mi) {
        int rbase = m0 + wm * 32 + mi * 16 + gp;
        float s0 = 1.f, s1 = 1.f;
        if (SCALE_OUT) {
            if (rbase < N_NODES)     s0 = g_dout_is[rbase];
            if (rbase + 8 < N_NODES) s1 = g_dout_is[rbase + 8];
        }
        #pragma unroll
        for (int ni = 0; ni < 4; ++ni) {
            int col = wn * 32 + ni * 8 + 2 * tg;
            if (rbase < N_NODES)
                *(float2*)&C[(size_t)rbase * 64 + col] =
                    make_float2(s0 * acc[mi][ni][0], s0 * acc[mi][ni][1]);
            if (rbase + 8 < N_NODES)
                *(float2*)&C[(size_t)(rbase + 8) * 64 + col] =
                    make_float2(s1 * acc[mi][ni][2], s1 * acc[mi][ni][3]);
        }
    }
}

template<bool SCALE_OUT>
__global__ __launch_bounds__(256, 2) void k_gemm_tc(
    const float* __restrict__ A, int lda, int acol,
    const float* __restrict__ W, int K,
    float* __restrict__ C)
{
    gemm_bf16_block<SCALE_OUT>(blockIdx.x, A, lda, acol, W, K, C);
}

// Fused: GEMM0 (dout * (feat @ W0)) + CSR bucketing; both depend only on k_scan.
__global__ __launch_bounds__(256, 2) void k_phase2(
    const float* __restrict__ feat, const float* __restrict__ W0,
    const int* __restrict__ src, const int* __restrict__ dst,
    int gemm_blocks, float* __restrict__ xs)
{
    if (blockIdx.x < (unsigned)gemm_blocks) {
        gemm_bf16_block<true>(blockIdx.x, feat, IN_F, 0, W0, IN_F, xs);
    } else {
        int e = (blockIdx.x - gemm_blocks) * 256 + threadIdx.x;
        if (e < N_EDGES) {
            int d = dst[e];
            int p = atomicAdd(&g_cursor[d], 1);
            g_esrc[g_csr_off[d] + p] = src[e];
        }
    }
}

// ---------------- CSR aggregation: one warp per node, half-warp per edge ----
// lanes 0..15 -> edge e, lanes 16..31 -> edge e+1; each lane loads float4
// (16 lanes x 16B = full 256B row). 8-edge unrolled body keeps ~8 independent
// row gathers in flight. Cross-half combine via shfl_xor(16).
template<bool DST_SCALE, bool RELU>
__global__ __launch_bounds__(256) void k_aggregate(
    const float* __restrict__ xin,          // [N, 64] (already dout-prescaled)
    float* __restrict__ out, int out_stride, int col_off,
    const float* __restrict__ bias)
{
    int gwarp = (blockIdx.x * blockDim.x + threadIdx.x) >> 5;
    int lane  = threadIdx.x & 31;
    if (gwarp >= N_NODES) return;

    const int half = lane >> 4;        // 0 or 1
    const int fcol = (lane & 15) << 2; // feature column base (0,4,..,60)

    int beg = g_csr_off[gwarp];
    int end = g_csr_off[gwarp + 1];

    float4 acc = make_float4(0.f, 0.f, 0.f, 0.f);
    int e = beg;

    // peel one edge if beg is odd (int2 alignment)
    if ((e & 1) && e < end) {
        if (half == 0) {
            int s = g_esrc[e];
            float4 v = *(const float4*)&xin[(size_t)s * 64 + fcol];
            acc.x += v.x; acc.y += v.y; acc.z += v.z; acc.w += v.w;
        }
        ++e;
    }

    // 8 edges per iteration: 4 int2 index loads, then 4 row gathers per half
    for (; e + 8 <= end; e += 8) {
        int2 ss[4];
        #pragma unroll
        for (int j = 0; j < 4; ++j) ss[j] = *(const int2*)&g_esrc[e + 2 * j];
        int s[4];
        #pragma unroll
        for (int j = 0; j < 4; ++j) s[j] = half ? ss[j].y : ss[j].x;
        float4 v[4];
        #pragma unroll
        for (int j = 0; j < 4; ++j)
            v[j] = *(const float4*)&xin[(size_t)s[j] * 64 + fcol];
        #pragma unroll
        for (int j = 0; j < 4; ++j) {
            acc.x += v[j].x; acc.y += v[j].y; acc.z += v[j].z; acc.w += v[j].w;
        }
    }
    // 2-edge loop
    for (; e + 2 <= end; e += 2) {
        int2 ss = *(const int2*)&g_esrc[e];
        int s = half ? ss.y : ss.x;
        float4 v = *(const float4*)&xin[(size_t)s * 64 + fcol];
        acc.x += v.x; acc.y += v.y; acc.z += v.z; acc.w += v.w;
    }
    // final odd edge
    if (e < end && half == 0) {
        int s = g_esrc[e];
        float4 v = *(const float4*)&xin[(size_t)s * 64 + fcol];
        acc.x += v.x; acc.y += v.y; acc.z += v.z; acc.w += v.w;
    }

    // combine the two halves
    acc.x += __shfl_xor_sync(0xffffffffu, acc.x, 16);
    acc.y += __shfl_xor_sync(0xffffffffu, acc.y, 16);
    acc.z += __shfl_xor_sync(0xffffffffu, acc.z, 16);
    acc.w += __shfl_xor_sync(0xffffffffu, acc.w, 16);

    if (DST_SCALE) {
        float sc = g_din_is[gwarp];
        acc.x *= sc; acc.y *= sc; acc.z *= sc; acc.w *= sc;
    }
    float4 b4 = *(const float4*)&bias[fcol];
    acc.x += b4.x; acc.y += b4.y; acc.z += b4.z; acc.w += b4.w;
    if (RELU) {
        acc.x = fmaxf(acc.x, 0.f);
        acc.y = fmaxf(acc.y, 0.f);
        acc.z = fmaxf(acc.z, 0.f);
        acc.w = fmaxf(acc.w, 0.f);
    }
    if (half == 0)
        *(float4*)&out[(size_t)gwarp * out_stride + col_off + fcol] = acc;
}

// ---------------- launch ----------------
extern "C" void kernel_launch(void* const* d_in, const int* in_sizes, int n_in,
                              void* d_out, int out_size)
{
    const float* feat  = (const float*)d_in[0];
    const int*   src   = (const int*)  d_in[1];
    const int*   dst   = (const int*)  d_in[2];
    const float* W[4]  = { (const float*)d_in[3], (const float*)d_in[5],
                           (const float*)d_in[7], (const float*)d_in[9] };
    const float* b[4]  = { (const float*)d_in[4], (const float*)d_in[6],
                           (const float*)d_in[8], (const float*)d_in[10] };
    const float* W_mlp = (const float*)d_in[11];
    const float* b_mlp = (const float*)d_in[12];
    float* out = (float*)d_out;

    float* xs;  cudaGetSymbolAddress((void**)&xs,  g_xs);
    float* cat; cudaGetSymbolAddress((void**)&cat, g_cat);
    float* y;   cudaGetSymbolAddress((void**)&y,   g_y);
    int* cnt_in;  cudaGetSymbolAddress((void**)&cnt_in,  g_cnt_in);
    int* cnt_out; cudaGetSymbolAddress((void**)&cnt_out, g_cnt_out);

    const int gemm_blocks = (N_NODES + 127) / 128;           // 391
    const int deg_blocks  = (N_EDGES + 255) / 256;           // 3125
    const int agg_blocks  = (N_NODES * 32 + 255) / 256;

    // --- CSR build; GEMM0 (dout-prescaled epilogue) fused with bucketing ---
    cudaMemsetAsync(cnt_in,  0, N_NODES * sizeof(int));
    cudaMemsetAsync(cnt_out, 0, N_NODES * sizeof(int));
    k_degree<<<deg_blocks, 256>>>(src, dst);
    k_scan  <<<1, 1024>>>();                                  // offsets + rsqrts + cursors
    k_phase2<<<gemm_blocks + deg_blocks, 256>>>(feat, W[0], src, dst, gemm_blocks, xs);

    // --- 4 GCN layers: all aggregates are scale-free gathers of prescaled xs ---
    k_aggregate<true, true><<<agg_blocks, 256>>>(xs, cat, CAT_F, 0, b[0]);
    for (int i = 1; i < 4; ++i) {
        k_gemm_tc<true><<<gemm_blocks, 256>>>(cat, CAT_F, (i - 1) * HID, W[i], HID, xs);
        k_aggregate<true, true><<<agg_blocks, 256>>>(xs, cat, CAT_F, i * HID, b[i]);
    }

    // --- final: y = cat @ W_mlp (unscaled), then plain aggregate + b_mlp ---
    k_gemm_tc<false><<<gemm_blocks, 256>>>(cat, CAT_F, 0, W_mlp, CAT_F, y);
    k_aggregate<false, false><<<agg_blocks, 256>>>(y, out, HID, 0, b_mlp);
}

// round 10
// speedup vs baseline: 1.1871x; 1.0188x over previous
#include <cuda_runtime.h>
#include <cuda_bf16.h>
#include <cuda_fp16.h>
#include <math.h>
#include <stdint.h>

#define N_NODES 50000
#define N_EDGES 800000
#define IN_F    256
#define HID     64
#define CAT_F   256   // 4 * HID

// ---------------- static scratch (no allocations allowed) ----------------
__device__ int    g_cnt_in [N_NODES];
__device__ int    g_cnt_out[N_NODES];
__device__ int    g_cursor [N_NODES];
__device__ int    g_csr_off[N_NODES + 1];
__device__ int    g_esrc   [N_EDGES];
__device__ float  g_dout_is[N_NODES];
__device__ float  g_din_is [N_NODES];
__device__ __half g_xs [N_NODES * HID];    // dout-prescaled GEMM output (fp16)
__device__ float  g_cat[N_NODES * CAT_F];  // JK concat of layer outputs (fp32)
__device__ __half g_y  [N_NODES * HID];    // cat @ W_mlp (fp16)

// ---------------- setup kernels ----------------
__global__ void k_degree(const int* __restrict__ src, const int* __restrict__ dst) {
    int e = blockIdx.x * blockDim.x + threadIdx.x;
    if (e < N_EDGES) {
        atomicAdd(&g_cnt_out[src[e]], 1);
        atomicAdd(&g_cnt_in [dst[e]], 1);
    }
}

// single block, 1024 threads: exclusive scan of in-degrees -> CSR offsets,
// rsqrt of clipped degrees, and cursor zeroing for bucketing.
__global__ void k_scan() {
    __shared__ int part[1024];
    const int CH = 52;                       // multiple of 4 for int4 loads
    int t = threadIdx.x;
    int beg = t * CH;
    int end = min(beg + CH, N_NODES);
    int s = 0;
    if (beg < N_NODES) {
        int i = beg;
        for (; i + 4 <= end; i += 4) {
            int4 c4 = *(const int4*)&g_cnt_in[i];
            s += c4.x + c4.y + c4.z + c4.w;
        }
        for (; i < end; ++i) s += g_cnt_in[i];
    }
    part[t] = s;
    __syncthreads();
    for (int d = 1; d < 1024; d <<= 1) {
        int v   = part[t];
        int add = (t >= d) ? part[t - d] : 0;
        __syncthreads();
        part[t] = v + add;
        __syncthreads();
    }
    int base = (t == 0) ? 0 : part[t - 1];
    for (int i = beg; i < end; ++i) {
        g_csr_off[i] = base;
        int cin = g_cnt_in[i];
        base += cin;
        g_cursor [i] = 0;
        g_din_is [i] = rsqrtf((float)max(cin, 1));
        g_dout_is[i] = rsqrtf((float)max(g_cnt_out[i], 1));
    }
    if (t == 1023) g_csr_off[N_NODES] = part[1023];
}

// ---------------- bf16 split helpers ----------------
__device__ __forceinline__ void split_bf16_pair(float x, float y,
                                                uint32_t& hi, uint32_t& lo) {
    __nv_bfloat16 hx = __float2bfloat16_rn(x);
    __nv_bfloat16 hy = __float2bfloat16_rn(y);
    __nv_bfloat16 lx = __float2bfloat16_rn(x - __bfloat162float(hx));
    __nv_bfloat16 ly = __float2bfloat16_rn(y - __bfloat162float(hy));
    __nv_bfloat162 h2 = __nv_bfloat162(hx, hy);
    __nv_bfloat162 l2 = __nv_bfloat162(lx, ly);
    hi = *(uint32_t*)&h2;
    lo = *(uint32_t*)&l2;
}

__device__ __forceinline__ void mma_bf16(float* d, const uint32_t* a, const uint32_t* b) {
    asm volatile(
        "mma.sync.aligned.m16n8k16.row.col.f32.bf16.bf16.f32 "
        "{%0,%1,%2,%3}, {%4,%5,%6,%7}, {%8,%9}, {%0,%1,%2,%3};"
        : "+f"(d[0]), "+f"(d[1]), "+f"(d[2]), "+f"(d[3])
        : "r"(a[0]), "r"(a[1]), "r"(a[2]), "r"(a[3]), "r"(b[0]), "r"(b[1]));
}

#define BF_LDS 20

// ---------------- tensor-core GEMM (3xBF16): C[N,64] = A @ W (fp16 out) -----
// BM=128, BN=64, BK=16, 256 threads (8 warps = 4M x 2N), per-warp 32x32.
// SCALE_OUT: multiply each output row by g_dout_is[row] before storing.
template<bool SCALE_OUT>
__device__ __forceinline__ void gemm_bf16_block(
    int bx,
    const float* __restrict__ A, int lda, int acol,
    const float* __restrict__ W, int K,
    __half* __restrict__ C)
{
    __shared__ uint32_t As[128 * BF_LDS];
    __shared__ uint32_t Bs[ 64 * BF_LDS];

    const int M    = N_NODES;
    const int tid  = threadIdx.x;
    const int lane = tid & 31;
    const int warp = tid >> 5;
    const int gp   = lane >> 2;
    const int tg   = lane & 3;
    const int wm   = warp & 3;
    const int wn   = warp >> 2;
    const int m0   = bx * 128;

    float acc[2][4][4];
    #pragma unroll
    for (int mi = 0; mi < 2; ++mi)
        #pragma unroll
        for (int ni = 0; ni < 4; ++ni)
            #pragma unroll
            for (int j = 0; j < 4; ++j) acc[mi][ni][j] = 0.f;

    for (int kk = 0; kk < K; kk += 16) {
        {
            int r   = tid >> 1;
            int h8  = tid & 1;
            int row = m0 + r;
            float4 v0 = make_float4(0.f, 0.f, 0.f, 0.f);
            float4 v1 = v0;
            if (row < M) {
                const float* p = &A[(size_t)row * lda + acol + kk + h8 * 8];
                v0 = *(const float4*)(p);
                v1 = *(const float4*)(p + 4);
            }
            uint32_t h[4], l[4];
            split_bf16_pair(v0.x, v0.y, h[0], l[0]);
            split_bf16_pair(v0.z, v0.w, h[1], l[1]);
            split_bf16_pair(v1.x, v1.y, h[2], l[2]);
            split_bf16_pair(v1.z, v1.w, h[3], l[3]);
            *(uint4*)&As[r * BF_LDS + h8 * 4]     = make_uint4(h[0], h[1], h[2], h[3]);
            *(uint4*)&As[r * BF_LDS + h8 * 4 + 8] = make_uint4(l[0], l[1], l[2], l[3]);
        }
        {
            int n  = tid & 63;
            int kq = tid >> 6;
            float w0 = W[(size_t)(kk + kq * 4 + 0) * 64 + n];
            float w1 = W[(size_t)(kk + kq * 4 + 1) * 64 + n];
            float w2 = W[(size_t)(kk + kq * 4 + 2) * 64 + n];
            float w3 = W[(size_t)(kk + kq * 4 + 3) * 64 + n];
            uint32_t h0, l0, h1, l1;
            split_bf16_pair(w0, w1, h0, l0);
            split_bf16_pair(w2, w3, h1, l1);
            Bs[n * BF_LDS + kq * 2]         = h0;
            Bs[n * BF_LDS + kq * 2 + 1]     = h1;
            Bs[n * BF_LDS + kq * 2 + 8]     = l0;
            Bs[n * BF_LDS + kq * 2 + 8 + 1] = l1;
        }
        __syncthreads();

        uint32_t ah[2][4], al[2][4];
        #pragma unroll
        for (int mi = 0; mi < 2; ++mi) {
            int b0 = (wm * 32 + mi * 16 + gp)     * BF_LDS;
            int b1 = (wm * 32 + mi * 16 + gp + 8) * BF_LDS;
            ah[mi][0] = As[b0 + tg];     ah[mi][1] = As[b1 + tg];
            ah[mi][2] = As[b0 + 4 + tg]; ah[mi][3] = As[b1 + 4 + tg];
            al[mi][0] = As[b0 + 8 + tg];     al[mi][1] = As[b1 + 8 + tg];
            al[mi][2] = As[b0 + 12 + tg];    al[mi][3] = As[b1 + 12 + tg];
        }
        #pragma unroll
        for (int ni = 0; ni < 4; ++ni) {
            int bb = (wn * 32 + ni * 8 + gp) * BF_LDS;
            uint32_t bh[2], bl[2];
            bh[0] = Bs[bb + tg]; bh[1] = Bs[bb + 4 + tg];
            bl[0] = Bs[bb + 8 + tg]; bl[1] = Bs[bb + 12 + tg];
            #pragma unroll
            for (int mi = 0; mi < 2; ++mi) {
                mma_bf16(acc[mi][ni], ah[mi], bh);
                mma_bf16(acc[mi][ni], al[mi], bh);
                mma_bf16(acc[mi][ni], ah[mi], bl);
            }
        }
        __syncthreads();
    }

    #pragma unroll
    for (int mi = 0; mi < 2; ++mi) {
        int rbase = m0 + wm * 32 + mi * 16 + gp;
        float s0 = 1.f, s1 = 1.f;
        if (SCALE_OUT) {
            if (rbase < N_NODES)     s0 = g_dout_is[rbase];
            if (rbase + 8 < N_NODES) s1 = g_dout_is[rbase + 8];
        }
        #pragma unroll
        for (int ni = 0; ni < 4; ++ni) {
            int col = wn * 32 + ni * 8 + 2 * tg;
            if (rbase < N_NODES)
                *(__half2*)&C[(size_t)rbase * 64 + col] =
                    __floats2half2_rn(s0 * acc[mi][ni][0], s0 * acc[mi][ni][1]);
            if (rbase + 8 < N_NODES)
                *(__half2*)&C[(size_t)(rbase + 8) * 64 + col] =
                    __floats2half2_rn(s1 * acc[mi][ni][2], s1 * acc[mi][ni][3]);
        }
    }
}

template<bool SCALE_OUT>
__global__ __launch_bounds__(256, 2) void k_gemm_tc(
    const float* __restrict__ A, int lda, int acol,
    const float* __restrict__ W, int K,
    __half* __restrict__ C)
{
    gemm_bf16_block<SCALE_OUT>(blockIdx.x, A, lda, acol, W, K, C);
}

// Fused: GEMM0 (dout * (feat @ W0)) + CSR bucketing; both depend only on k_scan.
__global__ __launch_bounds__(256, 2) void k_phase2(
    const float* __restrict__ feat, const float* __restrict__ W0,
    const int* __restrict__ src, const int* __restrict__ dst,
    int gemm_blocks, __half* __restrict__ xs)
{
    if (blockIdx.x < (unsigned)gemm_blocks) {
        gemm_bf16_block<true>(blockIdx.x, feat, IN_F, 0, W0, IN_F, xs);
    } else {
        int e = (blockIdx.x - gemm_blocks) * 256 + threadIdx.x;
        if (e < N_EDGES) {
            int d = dst[e];
            int p = atomicAdd(&g_cursor[d], 1);
            g_esrc[g_csr_off[d] + p] = src[e];
        }
    }
}

// ---------------- CSR aggregation: one warp per node, half-warp per edge ----
// fp16 input rows (128B). lanes 0..15 -> edge e, lanes 16..31 -> edge e+1;
// each lane loads uint2 = 4 halfs (16 lanes x 8B = full row). fp32 accumulate.
template<bool DST_SCALE, bool RELU>
__global__ __launch_bounds__(256) void k_aggregate(
    const __half* __restrict__ xin,         // [N, 64] fp16, dout-prescaled
    float* __restrict__ out, int out_stride, int col_off,
    const float* __restrict__ bias)
{
    int gwarp = (blockIdx.x * blockDim.x + threadIdx.x) >> 5;
    int lane  = threadIdx.x & 31;
    if (gwarp >= N_NODES) return;

    const int half = lane >> 4;        // 0 or 1
    const int f8   = lane & 15;        // 8-byte unit within row
    const int fcol = f8 << 2;          // feature column base (0,4,..,60)

    int beg = g_csr_off[gwarp];
    int end = g_csr_off[gwarp + 1];

    float4 acc = make_float4(0.f, 0.f, 0.f, 0.f);
    int e = beg;

    auto accum = [&](int s) {
        uint2 u = ((const uint2*)(xin + (size_t)s * 64))[f8];
        float2 p0 = __half22float2(*(__half2*)&u.x);
        float2 p1 = __half22float2(*(__half2*)&u.y);
        acc.x += p0.x; acc.y += p0.y; acc.z += p1.x; acc.w += p1.y;
    };

    // peel one edge if beg is odd (int2 alignment)
    if ((e & 1) && e < end) {
        if (half == 0) accum(g_esrc[e]);
        ++e;
    }

    // 8 edges per iteration: 4 int2 index loads, then 4 row gathers per half
    for (; e + 8 <= end; e += 8) {
        int2 ss[4];
        #pragma unroll
        for (int j = 0; j < 4; ++j) ss[j] = *(const int2*)&g_esrc[e + 2 * j];
        int s[4];
        #pragma unroll
        for (int j = 0; j < 4; ++j) s[j] = half ? ss[j].y : ss[j].x;
        uint2 u[4];
        #pragma unroll
        for (int j = 0; j < 4; ++j)
            u[j] = ((const uint2*)(xin + (size_t)s[j] * 64))[f8];
        #pragma unroll
        for (int j = 0; j < 4; ++j) {
            float2 p0 = __half22float2(*(__half2*)&u[j].x);
            float2 p1 = __half22float2(*(__half2*)&u[j].y);
            acc.x += p0.x; acc.y += p0.y; acc.z += p1.x; acc.w += p1.y;
        }
    }
    // 2-edge loop
    for (; e + 2 <= end; e += 2) {
        int2 ss = *(const int2*)&g_esrc[e];
        accum(half ? ss.y : ss.x);
    }
    // final odd edge
    if (e < end && half == 0) accum(g_esrc[e]);

    // combine the two halves
    acc.x += __shfl_xor_sync(0xffffffffu, acc.x, 16);
    acc.y += __shfl_xor_sync(0xffffffffu, acc.y, 16);
    acc.z += __shfl_xor_sync(0xffffffffu, acc.z, 16);
    acc.w += __shfl_xor_sync(0xffffffffu, acc.w, 16);

    if (DST_SCALE) {
        float sc = g_din_is[gwarp];
        acc.x *= sc; acc.y *= sc; acc.z *= sc; acc.w *= sc;
    }
    float4 b4 = *(const float4*)&bias[fcol];
    acc.x += b4.x; acc.y += b4.y; acc.z += b4.z; acc.w += b4.w;
    if (RELU) {
        acc.x = fmaxf(acc.x, 0.f);
        acc.y = fmaxf(acc.y, 0.f);
        acc.z = fmaxf(acc.z, 0.f);
        acc.w = fmaxf(acc.w, 0.f);
    }
    if (half == 0)
        *(float4*)&out[(size_t)gwarp * out_stride + col_off + fcol] = acc;
}

// ---------------- launch ----------------
extern "C" void kernel_launch(void* const* d_in, const int* in_sizes, int n_in,
                              void* d_out, int out_size)
{
    const float* feat  = (const float*)d_in[0];
    const int*   src   = (const int*)  d_in[1];
    const int*   dst   = (const int*)  d_in[2];
    const float* W[4]  = { (const float*)d_in[3], (const float*)d_in[5],
                           (const float*)d_in[7], (const float*)d_in[9] };
    const float* b[4]  = { (const float*)d_in[4], (const float*)d_in[6],
                           (const float*)d_in[8], (const float*)d_in[10] };
    const float* W_mlp = (const float*)d_in[11];
    const float* b_mlp = (const float*)d_in[12];
    float* out = (float*)d_out;

    __half* xs; cudaGetSymbolAddress((void**)&xs,  g_xs);
    float* cat; cudaGetSymbolAddress((void**)&cat, g_cat);
    __half* y;  cudaGetSymbolAddress((void**)&y,   g_y);
    int* cnt_in;  cudaGetSymbolAddress((void**)&cnt_in,  g_cnt_in);
    int* cnt_out; cudaGetSymbolAddress((void**)&cnt_out, g_cnt_out);

    const int gemm_blocks = (N_NODES + 127) / 128;           // 391
    const int deg_blocks  = (N_EDGES + 255) / 256;           // 3125
    const int agg_blocks  = (N_NODES * 32 + 255) / 256;

    // --- CSR build; GEMM0 (dout-prescaled epilogue) fused with bucketing ---
    cudaMemsetAsync(cnt_in,  0, N_NODES * sizeof(int));
    cudaMemsetAsync(cnt_out, 0, N_NODES * sizeof(int));
    k_degree<<<deg_blocks, 256>>>(src, dst);
    k_scan  <<<1, 1024>>>();                                  // offsets + rsqrts + cursors
    k_phase2<<<gemm_blocks + deg_blocks, 256>>>(feat, W[0], src, dst, gemm_blocks, xs);

    // --- 4 GCN layers: all aggregates are scale-free gathers of fp16 xs ---
    k_aggregate<true, true><<<agg_blocks, 256>>>(xs, cat, CAT_F, 0, b[0]);
    for (int i = 1; i < 4; ++i) {
        k_gemm_tc<true><<<gemm_blocks, 256>>>(cat, CAT_F, (i - 1) * HID, W[i], HID, xs);
        k_aggregate<true, true><<<agg_blocks, 256>>>(xs, cat, CAT_F, i * HID, b[i]);
    }

    // --- final: y = cat @ W_mlp (fp16, unscaled), then plain aggregate ---
    k_gemm_tc<false><<<gemm_blocks, 256>>>(cat, CAT_F, 0, W_mlp, CAT_F, y);
    k_aggregate<false, false><<<agg_blocks, 256>>>(y, out, HID, 0, b_mlp);
}